// round 14
// baseline (speedup 1.0000x reference)
#include <cuda_runtime.h>
#include <cuda_fp16.h>
#include <math.h>
#include <stdint.h>

// Problem constants
#define B_SZ    2
#define T_SEQ   1024
#define D_INF   1024
#define D_MEM   256
#define VOCAB   32000
#define PHASE_N 8
#define MARGIN_N 4
#define M_ROWS  (B_SZ * T_SEQ)   // 2048

// Output layout offsets (float elements)
#define OFF_MEM   0
#define OFF_SUM   131072
#define OFF_LB    655360
#define OFF_PH    66191360
#define OFF_WIN   66207744
#define OFF_MAR   131743744

// Scratch device globals
__device__ float g_k   [M_ROWS * D_MEM];
__device__ float g_v   [M_ROWS * D_MEM];
__device__ float g_beta[M_ROWS * D_MEM];
__device__ float g_lam [M_ROWS * D_MEM];
__device__ float g_sraw[M_ROWS * D_MEM];
__device__ float g_G1  [B_SZ * T_SEQ];   // k_{t-1}.k_t
__device__ float g_G2  [B_SZ * T_SEQ];   // k_{t-2}.k_t
__device__ float g_G3  [B_SZ * T_SEQ];   // k_{t-3}.k_t
__device__ float g_G4  [B_SZ * T_SEQ];   // k_{t-4}.k_t
// fp16 operands for the vocab GEMMs
__device__ __half g_A16 [M_ROWS * D_MEM];          // fp16(summary)
__device__ __half g_W1f [(size_t)VOCAB * D_MEM];   // fp16(Wlb)
__device__ __half g_W2f [(size_t)VOCAB * D_MEM];   // fp16(Wwin)

// ===================== helpers =====================
__device__ __forceinline__ uint32_t smem_u32(const void* p) {
    uint32_t a;
    asm("{ .reg .u64 t; cvta.to.shared.u64 t, %1; cvt.u32.u64 %0, t; }" : "=r"(a) : "l"(p));
    return a;
}
__device__ __forceinline__ void cp_async16(uint32_t dst, const void* src) {
    asm volatile("cp.async.cg.shared.global [%0], [%1], 16;" :: "r"(dst), "l"(src));
}
#define CP_COMMIT() asm volatile("cp.async.commit_group;" ::: "memory")
#define CP_WAIT(N)  asm volatile("cp.async.wait_group %0;" :: "n"(N) : "memory")

__device__ __forceinline__ void ldsm4(uint32_t* r, uint32_t addr) {
    asm volatile("ldmatrix.sync.aligned.m8n8.x4.shared.b16 {%0,%1,%2,%3}, [%4];"
        : "=r"(r[0]), "=r"(r[1]), "=r"(r[2]), "=r"(r[3]) : "r"(addr));
}
__device__ __forceinline__ void mma16816h(float* c, const uint32_t* a,
                                          uint32_t b0, uint32_t b1) {
    asm volatile(
        "mma.sync.aligned.m16n8k16.row.col.f32.f16.f16.f32 "
        "{%0,%1,%2,%3}, {%4,%5,%6,%7}, {%8,%9}, {%0,%1,%2,%3};"
        : "+f"(c[0]), "+f"(c[1]), "+f"(c[2]), "+f"(c[3])
        : "r"(a[0]), "r"(a[1]), "r"(a[2]), "r"(a[3]), "r"(b0), "r"(b1));
}

// packed f32x2 (FFMA2)
__device__ __forceinline__ unsigned long long pack2(float x, float y) {
    unsigned long long r;
    asm("mov.b64 %0, {%1, %2};" : "=l"(r) : "f"(x), "f"(y));
    return r;
}
__device__ __forceinline__ void unpack2(unsigned long long p, float& x, float& y) {
    asm("mov.b64 {%0, %1}, %2;" : "=f"(x), "=f"(y) : "l"(p));
}
__device__ __forceinline__ void ffma2(unsigned long long& d, unsigned long long a,
                                      unsigned long long b) {
    asm("fma.rn.f32x2 %0, %1, %2, %0;" : "+l"(d) : "l"(a), "l"(b));
}

// ===================== generic SIMT GEMM (small heads + summary) =====================
template <int ACT, bool H16>
__global__ __launch_bounds__(256)
void gemm_bias_act(const float* __restrict__ A, const float* __restrict__ B,
                   const float* __restrict__ bias, float* __restrict__ C,
                   int M, int N, int K, __half* __restrict__ gh)
{
    __shared__ float As[16][68];
    __shared__ float Bs[16][68];

    const int tid = threadIdx.x;
    const int m0 = blockIdx.y * 64;
    const int n0 = blockIdx.x * 64;
    const int ty = tid >> 4;
    const int tx = tid & 15;
    const int lr = tid >> 2;
    const int lc = (tid & 3) << 2;

    unsigned long long acc[4][2];
    #pragma unroll
    for (int i = 0; i < 4; i++) { acc[i][0] = 0ull; acc[i][1] = 0ull; }

    for (int k0 = 0; k0 < K; k0 += 16) {
        float4 av = *(const float4*)(A + (size_t)(m0 + lr) * K + k0 + lc);
        float4 bv = make_float4(0.f, 0.f, 0.f, 0.f);
        int bn = n0 + lr;
        if (bn < N) bv = *(const float4*)(B + (size_t)bn * K + k0 + lc);

        As[lc + 0][lr] = av.x; As[lc + 1][lr] = av.y;
        As[lc + 2][lr] = av.z; As[lc + 3][lr] = av.w;
        Bs[lc + 0][lr] = bv.x; Bs[lc + 1][lr] = bv.y;
        Bs[lc + 2][lr] = bv.z; Bs[lc + 3][lr] = bv.w;
        __syncthreads();

        #pragma unroll
        for (int kk = 0; kk < 16; kk++) {
            float4 a4  = *(const float4*)&As[kk][ty << 2];
            float2 b01 = *(const float2*)&Bs[kk][tx << 2];
            float2 b23 = *(const float2*)&Bs[kk][(tx << 2) + 2];
            unsigned long long B01 = pack2(b01.x, b01.y);
            unsigned long long B23 = pack2(b23.x, b23.y);
            unsigned long long a0 = pack2(a4.x, a4.x);
            unsigned long long a1 = pack2(a4.y, a4.y);
            unsigned long long a2 = pack2(a4.z, a4.z);
            unsigned long long a3 = pack2(a4.w, a4.w);
            ffma2(acc[0][0], a0, B01); ffma2(acc[0][1], a0, B23);
            ffma2(acc[1][0], a1, B01); ffma2(acc[1][1], a1, B23);
            ffma2(acc[2][0], a2, B01); ffma2(acc[2][1], a2, B23);
            ffma2(acc[3][0], a3, B01); ffma2(acc[3][1], a3, B23);
        }
        __syncthreads();
    }

    #pragma unroll
    for (int i = 0; i < 4; i++) {
        int m = m0 + (ty << 2) + i;
        float cs[4];
        unpack2(acc[i][0], cs[0], cs[1]);
        unpack2(acc[i][1], cs[2], cs[3]);
        #pragma unroll
        for (int j = 0; j < 4; j++) {
            int n = n0 + (tx << 2) + j;
            if (n < N) {
                float c = cs[j] + bias[n];
                if (ACT == 1) c = 1.f / (1.f + __expf(-c));
                else if (ACT == 2) c = tanhf(c);
                cs[j] = c;
                C[(size_t)m * N + n] = c;
            }
        }
        if (H16) {
            int nb = n0 + (tx << 2);
            __half2* ph = (__half2*)(gh + (size_t)m * 256 + nb);
            ph[0] = __halves2half2(__float2half_rn(cs[0]), __float2half_rn(cs[1]));
            ph[1] = __halves2half2(__float2half_rn(cs[2]), __float2half_rn(cs[3]));
        }
    }
}

// ===================== merged projections (grid.z selects head) =====================
__global__ __launch_bounds__(256)
void proj_gemm(const float* __restrict__ A,
               const float* __restrict__ W0, const float* __restrict__ W1,
               const float* __restrict__ W2, const float* __restrict__ W3,
               const float* __restrict__ b0, const float* __restrict__ b1,
               const float* __restrict__ b2, const float* __restrict__ b3,
               float* __restrict__ C0, float* __restrict__ C1,
               float* __restrict__ C2, float* __restrict__ C3)
{
    const int z = blockIdx.z;
    const float* B; const float* bias; float* C; int act;
    switch (z) {
        case 0:  B = W0; bias = b0; C = C0; act = 0; break;
        case 1:  B = W1; bias = b1; C = C1; act = 0; break;
        case 2:  B = W2; bias = b2; C = C2; act = 1; break;
        default: B = W3; bias = b3; C = C3; act = 1; break;
    }
    const int K = D_INF, N = D_MEM;

    __shared__ float As[16][68];
    __shared__ float Bs[16][68];

    const int tid = threadIdx.x;
    const int m0 = blockIdx.y * 64;
    const int n0 = blockIdx.x * 64;
    const int ty = tid >> 4;
    const int tx = tid & 15;
    const int lr = tid >> 2;
    const int lc = (tid & 3) << 2;

    unsigned long long acc[4][2];
    #pragma unroll
    for (int i = 0; i < 4; i++) { acc[i][0] = 0ull; acc[i][1] = 0ull; }

    for (int k0 = 0; k0 < K; k0 += 16) {
        float4 av = *(const float4*)(A + (size_t)(m0 + lr) * K + k0 + lc);
        float4 bv = *(const float4*)(B + (size_t)(n0 + lr) * K + k0 + lc);
        As[lc + 0][lr] = av.x; As[lc + 1][lr] = av.y;
        As[lc + 2][lr] = av.z; As[lc + 3][lr] = av.w;
        Bs[lc + 0][lr] = bv.x; Bs[lc + 1][lr] = bv.y;
        Bs[lc + 2][lr] = bv.z; Bs[lc + 3][lr] = bv.w;
        __syncthreads();
        #pragma unroll
        for (int kk = 0; kk < 16; kk++) {
            float4 a4  = *(const float4*)&As[kk][ty << 2];
            float2 b01 = *(const float2*)&Bs[kk][tx << 2];
            float2 b23 = *(const float2*)&Bs[kk][(tx << 2) + 2];
            unsigned long long B01 = pack2(b01.x, b01.y);
            unsigned long long B23 = pack2(b23.x, b23.y);
            unsigned long long a0 = pack2(a4.x, a4.x);
            unsigned long long a1 = pack2(a4.y, a4.y);
            unsigned long long a2 = pack2(a4.z, a4.z);
            unsigned long long a3 = pack2(a4.w, a4.w);
            ffma2(acc[0][0], a0, B01); ffma2(acc[0][1], a0, B23);
            ffma2(acc[1][0], a1, B01); ffma2(acc[1][1], a1, B23);
            ffma2(acc[2][0], a2, B01); ffma2(acc[2][1], a2, B23);
            ffma2(acc[3][0], a3, B01); ffma2(acc[3][1], a3, B23);
        }
        __syncthreads();
    }

    #pragma unroll
    for (int i = 0; i < 4; i++) {
        int m = m0 + (ty << 2) + i;
        float cs[4];
        unpack2(acc[i][0], cs[0], cs[1]);
        unpack2(acc[i][1], cs[2], cs[3]);
        #pragma unroll
        for (int j = 0; j < 4; j++) {
            int n = n0 + (tx << 2) + j;
            float c = cs[j] + bias[n];
            if (act == 1) c = 1.f / (1.f + __expf(-c));
            C[(size_t)m * N + n] = c;
        }
    }
}

// ===================== weight fp16 pre-convert (merged, grid.z selects W) ======
__global__ __launch_bounds__(256)
void convert_w16(const float* __restrict__ W1, const float* __restrict__ W2,
                 __half* __restrict__ o1, __half* __restrict__ o2)
{
    const float* W = blockIdx.z ? W2 : W1;
    __half* o = blockIdx.z ? o2 : o1;
    int i = blockIdx.x * 256 + threadIdx.x;     // [0, 32000*64)
    int n  = i >> 6;
    int kq = (i & 63) << 2;
    float4 w = *(const float4*)(W + (size_t)n * 256 + kq);
    size_t off = (size_t)n * 256 + kq;
    ((__half2*)(o + off))[0] = __halves2half2(__float2half_rn(w.x), __float2half_rn(w.y));
    ((__half2*)(o + off))[1] = __halves2half2(__float2half_rn(w.z), __float2half_rn(w.w));
}

// ===================== mma.sync vocab GEMM (fp16, 1-term) =====================
#define VK_PAD    40
#define VK_TILE   (128 * VK_PAD * 2)
#define VK_STAGE  (2 * VK_TILE)
#define VK_NSTAGE 4
#define VK_SMEM   (VK_NSTAGE * VK_STAGE)   // 81920

__global__ __launch_bounds__(256, 2)
void vocab_mma(const __half* __restrict__ gA,
               const __half* __restrict__ gB1, const __half* __restrict__ gB2,
               const float* __restrict__ bias1, const float* __restrict__ bias2,
               float* __restrict__ C1, float* __restrict__ C2)
{
    extern __shared__ __align__(16) char smem_raw[];
    const __half* gB = blockIdx.z ? gB2 : gB1;
    const float* bias = blockIdx.z ? bias2 : bias1;
    float* C = blockIdx.z ? C2 : C1;

    const int tid  = threadIdx.x;
    const int warp = tid >> 5, lane = tid & 31;
    const int wm = warp >> 2, wn = warp & 3;
    const int m0 = blockIdx.y * 128, n0 = blockIdx.x * 128;

    const uint32_t sbase = smem_u32(smem_raw);

    const int lrow = tid >> 1;
    const int lhal = tid & 1;

    float acc[4][4][4];
    #pragma unroll
    for (int i = 0; i < 4; i++)
        #pragma unroll
        for (int j = 0; j < 4; j++) {
            acc[i][j][0] = 0.f; acc[i][j][1] = 0.f;
            acc[i][j][2] = 0.f; acc[i][j][3] = 0.f;
        }

    auto issue_stage = [&](int kc) {
        const uint32_t st = sbase + (kc % VK_NSTAGE) * VK_STAGE;
        const size_t gAo = (size_t)(m0 + lrow) * 256 + kc * 32 + lhal * 16;
        const size_t gBo = (size_t)(n0 + lrow) * 256 + kc * 32 + lhal * 16;
        const uint32_t sd = st + lrow * (VK_PAD * 2) + lhal * 32;
        cp_async16(sd + 0 * VK_TILE,      gA + gAo);
        cp_async16(sd + 0 * VK_TILE + 16, gA + gAo + 8);
        cp_async16(sd + 1 * VK_TILE,      gB + gBo);
        cp_async16(sd + 1 * VK_TILE + 16, gB + gBo + 8);
    };

    issue_stage(0); CP_COMMIT();
    issue_stage(1); CP_COMMIT();
    issue_stage(2); CP_COMMIT();

    const uint32_t ar = wm * 64 + (lane & 15);
    const uint32_t ac16 = (lane >> 4) * 8;
    const int g = lane >> 3, r8 = lane & 7;
    const uint32_t br = wn * 32 + ((g >> 1) * 8) + r8;
    const uint32_t bc = (g & 1) * 8;

    #pragma unroll
    for (int kc = 0; kc < 8; kc++) {
        if (kc < 5)      { issue_stage(kc + 3); CP_COMMIT(); CP_WAIT(3); }
        else if (kc == 5){ CP_WAIT(2); }
        else if (kc == 6){ CP_WAIT(1); }
        else             { CP_WAIT(0); }
        __syncthreads();

        const uint32_t st = sbase + (kc % VK_NSTAGE) * VK_STAGE;
        const uint32_t tA = st;
        const uint32_t tB = st + VK_TILE;

        #pragma unroll
        for (int h = 0; h < 2; h++) {
            uint32_t a[4][4], b[2][4];
            #pragma unroll
            for (int fm = 0; fm < 4; fm++)
                ldsm4(a[fm], tA + ((ar + fm * 16) * VK_PAD + ac16 + h * 16) * 2);
            #pragma unroll
            for (int p = 0; p < 2; p++)
                ldsm4(b[p], tB + ((br + p * 16) * VK_PAD + bc + h * 16) * 2);

            #pragma unroll
            for (int fm = 0; fm < 4; fm++)
                #pragma unroll
                for (int fn = 0; fn < 4; fn++) {
                    const int p = fn >> 1, q = fn & 1;
                    mma16816h(acc[fm][fn], a[fm], b[p][q * 2], b[p][q * 2 + 1]);
                }
        }
        __syncthreads();
    }

    float2 bv[4];
    #pragma unroll
    for (int fn = 0; fn < 4; fn++)
        bv[fn] = *(const float2*)(bias + n0 + wn * 32 + fn * 8 + (lane & 3) * 2);

    #pragma unroll
    for (int fm = 0; fm < 4; fm++) {
        const int r0 = m0 + wm * 64 + fm * 16 + (lane >> 2);
        #pragma unroll
        for (int fn = 0; fn < 4; fn++) {
            const int col = n0 + wn * 32 + fn * 8 + (lane & 3) * 2;
            float2 v0 = make_float2(acc[fm][fn][0] + bv[fn].x, acc[fm][fn][1] + bv[fn].y);
            float2 v1 = make_float2(acc[fm][fn][2] + bv[fn].x, acc[fm][fn][3] + bv[fn].y);
            *(float2*)(C + (size_t)r0 * VOCAB + col)       = v0;
            *(float2*)(C + (size_t)(r0 + 8) * VOCAB + col) = v1;
        }
    }
}

// ===================== row L2-normalize =====================
__global__ __launch_bounds__(256)
void normalize_rows(float* __restrict__ X)
{
    int w = (blockIdx.x * blockDim.x + threadIdx.x) >> 5;
    int lane = threadIdx.x & 31;
    if (w >= M_ROWS) return;
    float* row = X + (size_t)w * D_MEM;
    float x[8];
    float ss = 0.f;
    #pragma unroll
    for (int j = 0; j < 8; j++) { x[j] = row[lane + 32 * j]; ss += x[j] * x[j]; }
    #pragma unroll
    for (int o = 16; o; o >>= 1) ss += __shfl_xor_sync(0xffffffffu, ss, o);
    float inv = 1.f / fmaxf(sqrtf(ss), 1e-12f);
    #pragma unroll
    for (int j = 0; j < 8; j++) row[lane + 32 * j] = x[j] * inv;
}

// ===================== k-neighbor Gram precompute (dist 1..4) ================
// Gi[b][t] = k_{t-i}.k_t for t>=i, else 0. One warp per (b,t): 2048 warps.
__global__ __launch_bounds__(256)
void gram_kernel(const float* __restrict__ Kn, float* __restrict__ G1,
                 float* __restrict__ G2, float* __restrict__ G3,
                 float* __restrict__ G4)
{
    int w = (blockIdx.x * blockDim.x + threadIdx.x) >> 5;  // 0..2047
    int lane = threadIdx.x & 31;
    int b = w >> 10, t = w & 1023;
    const float* kt = Kn + (size_t)b * T_SEQ * D_MEM + (size_t)t * D_MEM + lane;
    float d1 = 0.f, d2 = 0.f, d3 = 0.f, d4 = 0.f;
    #pragma unroll
    for (int j = 0; j < 8; j++) {
        float a0 = kt[32 * j];
        float p1 = (t >= 1) ? kt[32 * j - 1 * D_MEM] : 0.f;
        float p2 = (t >= 2) ? kt[32 * j - 2 * D_MEM] : 0.f;
        float p3 = (t >= 3) ? kt[32 * j - 3 * D_MEM] : 0.f;
        float p4 = (t >= 4) ? kt[32 * j - 4 * D_MEM] : 0.f;
        d1 = fmaf(a0, p1, d1);
        d2 = fmaf(a0, p2, d2);
        d3 = fmaf(a0, p3, d3);
        d4 = fmaf(a0, p4, d4);
    }
    #pragma unroll
    for (int o = 16; o; o >>= 1) {
        d1 += __shfl_xor_sync(0xffffffffu, d1, o);
        d2 += __shfl_xor_sync(0xffffffffu, d2, o);
        d3 += __shfl_xor_sync(0xffffffffu, d3, o);
        d4 += __shfl_xor_sync(0xffffffffu, d4, o);
    }
    if (lane == 0) { G1[w] = d1; G2[w] = d2; G3[w] = d3; G4[w] = d4; }
}

// ===================== gated delta-rule scan (distance-4 pipelined) ===========
// read_s = t1234*D_s + (t123*c4)*G4_s + (t12*c3)*G3_s + (t1*c2)*G2_s + c1*G1_s
// with D_s = M^(s-4).k_s, ti.. = products of l_{s-1}..l_{s-i}, ci = corr_{s-i}.
// 4 independent butterflies in flight -> SHFL issue-bound, not latency-bound.
// Critical recurrence: c1 -> read (1 FMA) -> corr. Ring-of-5, all static.
#define SCAN_BODY(C, C4, S) do {                                              \
    const int ii_ = ((S) + 5 < T_SEQ) ? (S) + 5 : (T_SEQ - 1);                \
    float nk_[8];                                                             \
    _Pragma("unroll")                                                         \
    for (int j = 0; j < 8; j++) nk_[j] = kb[(size_t)ii_ * D_MEM + 32 * j];    \
    const float nv_ = vb[(size_t)ii_ * D_MEM];                                \
    const float nb_ = bbp[(size_t)ii_ * D_MEM];                               \
    const float nl_ = lb[(size_t)ii_ * D_MEM];                                \
    const float ng1_ = g1b[ii_], ng2_ = g2b[ii_];                             \
    const float ng3_ = g3b[ii_], ng4_ = g4b[ii_];                             \
    float ua_ = 0.f, ub_ = 0.f;                                               \
    _Pragma("unroll")                                                         \
    for (int j = 0; j < 8; j += 2) {                                          \
        ua_ = fmaf(m[j], kr##C4[j], ua_);                                     \
        ub_ = fmaf(m[j + 1], kr##C4[j + 1], ub_);                             \
    }                                                                         \
    float base_ = fmaf(t1234, Dcur, (t123 * c4) * g4r##C);                    \
    base_ = fmaf(t12 * c3, g3r##C, base_);                                    \
    base_ = fmaf(t1 * c2, g2r##C, base_);                                     \
    const float read_ = fmaf(c1, g1r##C, base_);                              \
    const float corr_ = (vr##C - read_) * br##C;                              \
    if (lane == 0) sb[(size_t)(S) * D_MEM] = fmaf(lr##C, read_, corr_);       \
    _Pragma("unroll")                                                         \
    for (int j = 0; j < 8; j++)                                               \
        m[j] = fmaf(m[j], lr##C, corr_ * kr##C[j]);                           \
    _Pragma("unroll")                                                         \
    for (int o = 16; o; o >>= 1) {                                            \
        ua_ += __shfl_xor_sync(0xffffffffu, ua_, o);                          \
        ub_ += __shfl_xor_sync(0xffffffffu, ub_, o);                          \
    }                                                                         \
    Dcur = Dn1; Dn1 = Dn2; Dn2 = Dn3; Dn3 = ua_ + ub_;                        \
    c4 = c3; c3 = c2; c2 = c1; c1 = corr_;                                    \
    t1234 = lr##C * t123; t123 = lr##C * t12; t12 = lr##C * t1; t1 = lr##C;   \
    _Pragma("unroll")                                                         \
    for (int j = 0; j < 8; j++) kr##C[j] = nk_[j];                            \
    vr##C = nv_; br##C = nb_; lr##C = nl_;                                    \
    g1r##C = ng1_; g2r##C = ng2_; g3r##C = ng3_; g4r##C = ng4_;               \
} while (0)

#define RELOAD_SLOT(C, II) do {                                               \
    _Pragma("unroll")                                                         \
    for (int j = 0; j < 8; j++) kr##C[j] = kb[(size_t)(II) * D_MEM + 32 * j]; \
    vr##C = vb[(size_t)(II) * D_MEM];                                         \
    br##C = bbp[(size_t)(II) * D_MEM];                                        \
    lr##C = lb[(size_t)(II) * D_MEM];                                         \
    g1r##C = g1b[II]; g2r##C = g2b[II];                                       \
    g3r##C = g3b[II]; g4r##C = g4b[II];                                       \
} while (0)

__global__ __launch_bounds__(128)
void scan_kernel(const float* __restrict__ Kn, const float* __restrict__ V,
                 const float* __restrict__ Beta, const float* __restrict__ Lam,
                 const float* __restrict__ G1, const float* __restrict__ G2,
                 const float* __restrict__ G3, const float* __restrict__ G4,
                 const float* __restrict__ Mem0, float* __restrict__ Sraw,
                 float* __restrict__ MemOut)
{
    const int wid  = threadIdx.x >> 5;
    const int lane = threadIdx.x & 31;
    const int wg = blockIdx.x * 4 + wid;
    const int b = wg >> 8;
    const int r = wg & 255;

    const float* kb  = Kn   + (size_t)b * T_SEQ * D_MEM + lane;
    const float* vb  = V    + (size_t)b * T_SEQ * D_MEM + r;
    const float* bbp = Beta + (size_t)b * T_SEQ * D_MEM + r;
    const float* lb  = Lam  + (size_t)b * T_SEQ * D_MEM + r;
    const float* g1b = G1 + (size_t)b * T_SEQ;
    const float* g2b = G2 + (size_t)b * T_SEQ;
    const float* g3b = G3 + (size_t)b * T_SEQ;
    const float* g4b = G4 + (size_t)b * T_SEQ;
    float* sb = Sraw + (size_t)b * T_SEQ * D_MEM + r;

    float m[8];
    #pragma unroll
    for (int j = 0; j < 8; j++)
        m[j] = Mem0[(size_t)b * D_MEM * D_MEM + (size_t)r * D_MEM + lane + 32 * j];

    // rings of 5 (all static)
    float kr0[8], kr1[8], kr2[8], kr3[8], kr4[8];
    float vr0, vr1, vr2, vr3, vr4;
    float br0, br1, br2, br3, br4;
    float lr0, lr1, lr2, lr3, lr4;
    float g1r0, g1r1, g1r2, g1r3, g1r4;
    float g2r0, g2r1, g2r2, g2r3, g2r4;
    float g3r0, g3r1, g3r2, g3r3, g3r4;
    float g4r0, g4r1, g4r2, g4r3, g4r4;
    RELOAD_SLOT(0, 0); RELOAD_SLOT(1, 1); RELOAD_SLOT(2, 2);
    RELOAD_SLOT(3, 3); RELOAD_SLOT(4, 4);

    // ---- boot block: A_i = M^(0).k_i for i = 0..4 (5 interleaved reductions)
    float A0 = 0.f, A1 = 0.f, A2 = 0.f, A3 = 0.f, A4 = 0.f;
    #pragma unroll
    for (int j = 0; j < 8; j++) {
        A0 = fmaf(m[j], kr0[j], A0);
        A1 = fmaf(m[j], kr1[j], A1);
        A2 = fmaf(m[j], kr2[j], A2);
        A3 = fmaf(m[j], kr3[j], A3);
        A4 = fmaf(m[j], kr4[j], A4);
    }
    #pragma unroll
    for (int o = 16; o; o >>= 1) {
        A0 += __shfl_xor_sync(0xffffffffu, A0, o);
        A1 += __shfl_xor_sync(0xffffffffu, A1, o);
        A2 += __shfl_xor_sync(0xffffffffu, A2, o);
        A3 += __shfl_xor_sync(0xffffffffu, A3, o);
        A4 += __shfl_xor_sync(0xffffffffu, A4, o);
    }

    // ---- boot step 0 ----
    const float l0s = lr0;
    const float read0 = A0;
    const float corr0 = (vr0 - read0) * br0;
    if (lane == 0) sb[0] = fmaf(l0s, read0, corr0);
    #pragma unroll
    for (int j = 0; j < 8; j++) m[j] = fmaf(m[j], l0s, corr0 * kr0[j]);   // M^(1)
    RELOAD_SLOT(0, 5);

    // ---- boot step 1 (D5 partials on M^(1) with k5 in slot 0) ----
    float u5a = 0.f, u5b = 0.f;
    #pragma unroll
    for (int j = 0; j < 8; j += 2) {
        u5a = fmaf(m[j], kr0[j], u5a);
        u5b = fmaf(m[j + 1], kr0[j + 1], u5b);
    }
    const float l1s = lr1;
    const float read1 = fmaf(l0s, A1, corr0 * g1r1);
    const float corr1 = (vr1 - read1) * br1;
    if (lane == 0) sb[D_MEM] = fmaf(l1s, read1, corr1);
    #pragma unroll
    for (int j = 0; j < 8; j++) m[j] = fmaf(m[j], l1s, corr1 * kr1[j]);   // M^(2)
    #pragma unroll
    for (int o = 16; o; o >>= 1) {
        u5a += __shfl_xor_sync(0xffffffffu, u5a, o);
        u5b += __shfl_xor_sync(0xffffffffu, u5b, o);
    }
    const float D5 = u5a + u5b;
    RELOAD_SLOT(1, 6);

    // ---- boot step 2 (D6 partials on M^(2) with k6 in slot 1) ----
    float u6a = 0.f, u6b = 0.f;
    #pragma unroll
    for (int j = 0; j < 8; j += 2) {
        u6a = fmaf(m[j], kr1[j], u6a);
        u6b = fmaf(m[j + 1], kr1[j + 1], u6b);
    }
    const float l2s = lr2;
    const float read2 = fmaf(l1s, fmaf(l0s, A2, corr0 * g2r2), corr1 * g1r2);
    const float corr2 = (vr2 - read2) * br2;
    if (lane == 0) sb[2 * D_MEM] = fmaf(l2s, read2, corr2);
    #pragma unroll
    for (int j = 0; j < 8; j++) m[j] = fmaf(m[j], l2s, corr2 * kr2[j]);   // M^(3)
    #pragma unroll
    for (int o = 16; o; o >>= 1) {
        u6a += __shfl_xor_sync(0xffffffffu, u6a, o);
        u6b += __shfl_xor_sync(0xffffffffu, u6b, o);
    }
    const float D6 = u6a + u6b;
    RELOAD_SLOT(2, 7);

    // ---- boot step 3 (D7 partials on M^(3) with k7 in slot 2) ----
    float u7a = 0.f, u7b = 0.f;
    #pragma unroll
    for (int j = 0; j < 8; j += 2) {
        u7a = fmaf(m[j], kr2[j], u7a);
        u7b = fmaf(m[j + 1], kr2[j + 1], u7b);
    }
    const float l3s = lr3;
    float in3 = fmaf(l1s, fmaf(l0s, A3, corr0 * g3r3), corr1 * g2r3);
    const float read3 = fmaf(l2s, in3, corr2 * g1r3);
    const float corr3 = (vr3 - read3) * br3;
    if (lane == 0) sb[3 * D_MEM] = fmaf(l3s, read3, corr3);
    #pragma unroll
    for (int j = 0; j < 8; j++) m[j] = fmaf(m[j], l3s, corr3 * kr3[j]);   // M^(4)
    #pragma unroll
    for (int o = 16; o; o >>= 1) {
        u7a += __shfl_xor_sync(0xffffffffu, u7a, o);
        u7b += __shfl_xor_sync(0xffffffffu, u7b, o);
    }
    const float D7 = u7a + u7b;
    RELOAD_SLOT(3, 8);

    // ---- seed steady-state scalars (entering s = 4) ----
    float Dcur = A4, Dn1 = D5, Dn2 = D6, Dn3 = D7;
    float c1 = corr3, c2 = corr2, c3 = corr1, c4 = corr0;
    float t1 = l3s;
    float t12 = l3s * l2s;
    float t123 = t12 * l1s;
    float t1234 = t123 * l0s;

    // ---- steady loop: s = 4 .. 1023 (1020 = 204 * 5) ----
    for (int s = 4; s < T_SEQ; s += 5) {
        SCAN_BODY(4, 3, s);
        SCAN_BODY(0, 4, s + 1);
        SCAN_BODY(1, 0, s + 2);
        SCAN_BODY(2, 1, s + 3);
        SCAN_BODY(3, 2, s + 4);
    }

    #pragma unroll
    for (int j = 0; j < 8; j++)
        MemOut[(size_t)b * D_MEM * D_MEM + (size_t)r * D_MEM + lane + 32 * j] = m[j];
}

// ===================== launch =====================
extern "C" void kernel_launch(void* const* d_in, const int* in_sizes, int n_in,
                              void* d_out, int out_size)
{
    const float* cf    = (const float*)d_in[0];
    const float* mem0  = (const float*)d_in[1];
    const float* Wk    = (const float*)d_in[2];
    const float* bk    = (const float*)d_in[3];
    const float* Wv    = (const float*)d_in[4];
    const float* bv    = (const float*)d_in[5];
    const float* Wbeta = (const float*)d_in[6];
    const float* bbeta = (const float*)d_in[7];
    const float* Wlam  = (const float*)d_in[8];
    const float* blam  = (const float*)d_in[9];
    const float* Wsum  = (const float*)d_in[10];
    const float* bsum  = (const float*)d_in[11];
    const float* Wlb   = (const float*)d_in[12];
    const float* blb   = (const float*)d_in[13];
    const float* Wph   = (const float*)d_in[14];
    const float* bph   = (const float*)d_in[15];
    const float* Wwin  = (const float*)d_in[16];
    const float* bwin  = (const float*)d_in[17];
    const float* Wmar  = (const float*)d_in[18];
    const float* bmar  = (const float*)d_in[19];

    float* out = (float*)d_out;
    float* out_mem = out + OFF_MEM;
    float* out_sum = out + OFF_SUM;
    float* out_lb  = out + OFF_LB;
    float* out_ph  = out + OFF_PH;
    float* out_win = out + OFF_WIN;
    float* out_mar = out + OFF_MAR;

    float *pk, *pv, *pb, *pl, *ps, *pG1, *pG2, *pG3, *pG4;
    __half *pA16, *pW1, *pW2;
    cudaGetSymbolAddress((void**)&pk, g_k);
    cudaGetSymbolAddress((void**)&pv, g_v);
    cudaGetSymbolAddress((void**)&pb, g_beta);
    cudaGetSymbolAddress((void**)&pl, g_lam);
    cudaGetSymbolAddress((void**)&ps, g_sraw);
    cudaGetSymbolAddress((void**)&pG1, g_G1);
    cudaGetSymbolAddress((void**)&pG2, g_G2);
    cudaGetSymbolAddress((void**)&pG3, g_G3);
    cudaGetSymbolAddress((void**)&pG4, g_G4);
    cudaGetSymbolAddress((void**)&pA16, g_A16);
    cudaGetSymbolAddress((void**)&pW1, g_W1f);
    cudaGetSymbolAddress((void**)&pW2, g_W2f);

    cudaFuncSetAttribute(vocab_mma, cudaFuncAttributeMaxDynamicSharedMemorySize, VK_SMEM);

    // weight pre-convert (merged; independent of the recurrence path)
    convert_w16<<<dim3(8000, 1, 2), 256>>>(Wlb, Wwin, pW1, pW2);

    // projections (merged)
    proj_gemm<<<dim3(4, 32, 4), 256>>>(cf, Wk, Wv, Wbeta, Wlam,
                                       bk, bv, bbeta, blam,
                                       pk, pv, pb, pl);

    normalize_rows<<<256, 256>>>(pk);

    // k-neighbor Gram terms (dist 1..4)
    gram_kernel<<<256, 256>>>(pk, pG1, pG2, pG3, pG4);

    scan_kernel<<<128, 128>>>(pk, pv, pb, pl, pG1, pG2, pG3, pG4,
                              mem0, ps, out_mem);

    // summary GEMM (tanh) + fp16 side output
    gemm_bias_act<2, true><<<dim3(4, 32), 256>>>(ps, Wsum, bsum, out_sum,
                                                 M_ROWS, D_MEM, D_MEM, pA16);

    // both vocab GEMMs in one launch (grid.z selects head)
    vocab_mma<<<dim3(250, 16, 2), 256, VK_SMEM>>>(pA16, pW1, pW2, blb, bwin,
                                                  out_lb, out_win);

    // small heads
    gemm_bias_act<0, false><<<dim3(1, 32), 256>>>(out_sum, Wph,  bph,  out_ph,
                                                  M_ROWS, PHASE_N, D_MEM, nullptr);
    gemm_bias_act<0, false><<<dim3(1, 32), 256>>>(out_sum, Wmar, bmar, out_mar,
                                                  M_ROWS, MARGIN_N, D_MEM, nullptr);
}

// round 16
// speedup vs baseline: 1.0853x; 1.0853x over previous
#include <cuda_runtime.h>
#include <cuda_fp16.h>
#include <math.h>
#include <stdint.h>

// Problem constants
#define B_SZ    2
#define T_SEQ   1024
#define D_INF   1024
#define D_MEM   256
#define VOCAB   32000
#define PHASE_N 8
#define MARGIN_N 4
#define M_ROWS  (B_SZ * T_SEQ)   // 2048

// Output layout offsets (float elements)
#define OFF_MEM   0
#define OFF_SUM   131072
#define OFF_LB    655360
#define OFF_PH    66191360
#define OFF_WIN   66207744
#define OFF_MAR   131743744

// Scratch device globals
__device__ float g_k   [M_ROWS * D_MEM];
__device__ float g_v   [M_ROWS * D_MEM];
__device__ float g_beta[M_ROWS * D_MEM];
__device__ float g_lam [M_ROWS * D_MEM];
__device__ float g_sraw[M_ROWS * D_MEM];
__device__ float4 g_Gv [B_SZ * T_SEQ];   // (G1,G2,G3,G4)[b][t] = k_{t-i}.k_t
// fp16 operands for the vocab GEMMs
__device__ __half g_A16 [M_ROWS * D_MEM];          // fp16(summary)
__device__ __half g_W1f [(size_t)VOCAB * D_MEM];   // fp16(Wlb)
__device__ __half g_W2f [(size_t)VOCAB * D_MEM];   // fp16(Wwin)

// ===================== helpers =====================
__device__ __forceinline__ uint32_t smem_u32(const void* p) {
    uint32_t a;
    asm("{ .reg .u64 t; cvta.to.shared.u64 t, %1; cvt.u32.u64 %0, t; }" : "=r"(a) : "l"(p));
    return a;
}
__device__ __forceinline__ void cp_async16(uint32_t dst, const void* src) {
    asm volatile("cp.async.cg.shared.global [%0], [%1], 16;" :: "r"(dst), "l"(src));
}
#define CP_COMMIT() asm volatile("cp.async.commit_group;" ::: "memory")
#define CP_WAIT(N)  asm volatile("cp.async.wait_group %0;" :: "n"(N) : "memory")

__device__ __forceinline__ void ldsm4(uint32_t* r, uint32_t addr) {
    asm volatile("ldmatrix.sync.aligned.m8n8.x4.shared.b16 {%0,%1,%2,%3}, [%4];"
        : "=r"(r[0]), "=r"(r[1]), "=r"(r[2]), "=r"(r[3]) : "r"(addr));
}
__device__ __forceinline__ void mma16816h(float* c, const uint32_t* a,
                                          uint32_t b0, uint32_t b1) {
    asm volatile(
        "mma.sync.aligned.m16n8k16.row.col.f32.f16.f16.f32 "
        "{%0,%1,%2,%3}, {%4,%5,%6,%7}, {%8,%9}, {%0,%1,%2,%3};"
        : "+f"(c[0]), "+f"(c[1]), "+f"(c[2]), "+f"(c[3])
        : "r"(a[0]), "r"(a[1]), "r"(a[2]), "r"(a[3]), "r"(b0), "r"(b1));
}

// packed f32x2 (FFMA2)
__device__ __forceinline__ unsigned long long pack2(float x, float y) {
    unsigned long long r;
    asm("mov.b64 %0, {%1, %2};" : "=l"(r) : "f"(x), "f"(y));
    return r;
}
__device__ __forceinline__ void unpack2(unsigned long long p, float& x, float& y) {
    asm("mov.b64 {%0, %1}, %2;" : "=f"(x), "=f"(y) : "l"(p));
}
__device__ __forceinline__ void ffma2(unsigned long long& d, unsigned long long a,
                                      unsigned long long b) {
    asm("fma.rn.f32x2 %0, %1, %2, %0;" : "+l"(d) : "l"(a), "l"(b));
}

// ===================== generic SIMT GEMM (small heads + summary) =====================
template <int ACT, bool H16>
__global__ __launch_bounds__(256)
void gemm_bias_act(const float* __restrict__ A, const float* __restrict__ B,
                   const float* __restrict__ bias, float* __restrict__ C,
                   int M, int N, int K, __half* __restrict__ gh)
{
    __shared__ float As[16][68];
    __shared__ float Bs[16][68];

    const int tid = threadIdx.x;
    const int m0 = blockIdx.y * 64;
    const int n0 = blockIdx.x * 64;
    const int ty = tid >> 4;
    const int tx = tid & 15;
    const int lr = tid >> 2;
    const int lc = (tid & 3) << 2;

    unsigned long long acc[4][2];
    #pragma unroll
    for (int i = 0; i < 4; i++) { acc[i][0] = 0ull; acc[i][1] = 0ull; }

    for (int k0 = 0; k0 < K; k0 += 16) {
        float4 av = *(const float4*)(A + (size_t)(m0 + lr) * K + k0 + lc);
        float4 bv = make_float4(0.f, 0.f, 0.f, 0.f);
        int bn = n0 + lr;
        if (bn < N) bv = *(const float4*)(B + (size_t)bn * K + k0 + lc);

        As[lc + 0][lr] = av.x; As[lc + 1][lr] = av.y;
        As[lc + 2][lr] = av.z; As[lc + 3][lr] = av.w;
        Bs[lc + 0][lr] = bv.x; Bs[lc + 1][lr] = bv.y;
        Bs[lc + 2][lr] = bv.z; Bs[lc + 3][lr] = bv.w;
        __syncthreads();

        #pragma unroll
        for (int kk = 0; kk < 16; kk++) {
            float4 a4  = *(const float4*)&As[kk][ty << 2];
            float2 b01 = *(const float2*)&Bs[kk][tx << 2];
            float2 b23 = *(const float2*)&Bs[kk][(tx << 2) + 2];
            unsigned long long B01 = pack2(b01.x, b01.y);
            unsigned long long B23 = pack2(b23.x, b23.y);
            unsigned long long a0 = pack2(a4.x, a4.x);
            unsigned long long a1 = pack2(a4.y, a4.y);
            unsigned long long a2 = pack2(a4.z, a4.z);
            unsigned long long a3 = pack2(a4.w, a4.w);
            ffma2(acc[0][0], a0, B01); ffma2(acc[0][1], a0, B23);
            ffma2(acc[1][0], a1, B01); ffma2(acc[1][1], a1, B23);
            ffma2(acc[2][0], a2, B01); ffma2(acc[2][1], a2, B23);
            ffma2(acc[3][0], a3, B01); ffma2(acc[3][1], a3, B23);
        }
        __syncthreads();
    }

    #pragma unroll
    for (int i = 0; i < 4; i++) {
        int m = m0 + (ty << 2) + i;
        float cs[4];
        unpack2(acc[i][0], cs[0], cs[1]);
        unpack2(acc[i][1], cs[2], cs[3]);
        #pragma unroll
        for (int j = 0; j < 4; j++) {
            int n = n0 + (tx << 2) + j;
            if (n < N) {
                float c = cs[j] + bias[n];
                if (ACT == 1) c = 1.f / (1.f + __expf(-c));
                else if (ACT == 2) c = tanhf(c);
                cs[j] = c;
                C[(size_t)m * N + n] = c;
            }
        }
        if (H16) {
            int nb = n0 + (tx << 2);
            __half2* ph = (__half2*)(gh + (size_t)m * 256 + nb);
            ph[0] = __halves2half2(__float2half_rn(cs[0]), __float2half_rn(cs[1]));
            ph[1] = __halves2half2(__float2half_rn(cs[2]), __float2half_rn(cs[3]));
        }
    }
}

// ===================== merged projections (grid.z selects head) =====================
__global__ __launch_bounds__(256)
void proj_gemm(const float* __restrict__ A,
               const float* __restrict__ W0, const float* __restrict__ W1,
               const float* __restrict__ W2, const float* __restrict__ W3,
               const float* __restrict__ b0, const float* __restrict__ b1,
               const float* __restrict__ b2, const float* __restrict__ b3,
               float* __restrict__ C0, float* __restrict__ C1,
               float* __restrict__ C2, float* __restrict__ C3)
{
    const int z = blockIdx.z;
    const float* B; const float* bias; float* C; int act;
    switch (z) {
        case 0:  B = W0; bias = b0; C = C0; act = 0; break;
        case 1:  B = W1; bias = b1; C = C1; act = 0; break;
        case 2:  B = W2; bias = b2; C = C2; act = 1; break;
        default: B = W3; bias = b3; C = C3; act = 1; break;
    }
    const int K = D_INF, N = D_MEM;

    __shared__ float As[16][68];
    __shared__ float Bs[16][68];

    const int tid = threadIdx.x;
    const int m0 = blockIdx.y * 64;
    const int n0 = blockIdx.x * 64;
    const int ty = tid >> 4;
    const int tx = tid & 15;
    const int lr = tid >> 2;
    const int lc = (tid & 3) << 2;

    unsigned long long acc[4][2];
    #pragma unroll
    for (int i = 0; i < 4; i++) { acc[i][0] = 0ull; acc[i][1] = 0ull; }

    for (int k0 = 0; k0 < K; k0 += 16) {
        float4 av = *(const float4*)(A + (size_t)(m0 + lr) * K + k0 + lc);
        float4 bv = *(const float4*)(B + (size_t)(n0 + lr) * K + k0 + lc);
        As[lc + 0][lr] = av.x; As[lc + 1][lr] = av.y;
        As[lc + 2][lr] = av.z; As[lc + 3][lr] = av.w;
        Bs[lc + 0][lr] = bv.x; Bs[lc + 1][lr] = bv.y;
        Bs[lc + 2][lr] = bv.z; Bs[lc + 3][lr] = bv.w;
        __syncthreads();
        #pragma unroll
        for (int kk = 0; kk < 16; kk++) {
            float4 a4  = *(const float4*)&As[kk][ty << 2];
            float2 b01 = *(const float2*)&Bs[kk][tx << 2];
            float2 b23 = *(const float2*)&Bs[kk][(tx << 2) + 2];
            unsigned long long B01 = pack2(b01.x, b01.y);
            unsigned long long B23 = pack2(b23.x, b23.y);
            unsigned long long a0 = pack2(a4.x, a4.x);
            unsigned long long a1 = pack2(a4.y, a4.y);
            unsigned long long a2 = pack2(a4.z, a4.z);
            unsigned long long a3 = pack2(a4.w, a4.w);
            ffma2(acc[0][0], a0, B01); ffma2(acc[0][1], a0, B23);
            ffma2(acc[1][0], a1, B01); ffma2(acc[1][1], a1, B23);
            ffma2(acc[2][0], a2, B01); ffma2(acc[2][1], a2, B23);
            ffma2(acc[3][0], a3, B01); ffma2(acc[3][1], a3, B23);
        }
        __syncthreads();
    }

    #pragma unroll
    for (int i = 0; i < 4; i++) {
        int m = m0 + (ty << 2) + i;
        float cs[4];
        unpack2(acc[i][0], cs[0], cs[1]);
        unpack2(acc[i][1], cs[2], cs[3]);
        #pragma unroll
        for (int j = 0; j < 4; j++) {
            int n = n0 + (tx << 2) + j;
            float c = cs[j] + bias[n];
            if (act == 1) c = 1.f / (1.f + __expf(-c));
            C[(size_t)m * N + n] = c;
        }
    }
}

// ===================== weight fp16 pre-convert (merged, grid.z selects W) ======
__global__ __launch_bounds__(256)
void convert_w16(const float* __restrict__ W1, const float* __restrict__ W2,
                 __half* __restrict__ o1, __half* __restrict__ o2)
{
    const float* W = blockIdx.z ? W2 : W1;
    __half* o = blockIdx.z ? o2 : o1;
    int i = blockIdx.x * 256 + threadIdx.x;     // [0, 32000*64)
    int n  = i >> 6;
    int kq = (i & 63) << 2;
    float4 w = *(const float4*)(W + (size_t)n * 256 + kq);
    size_t off = (size_t)n * 256 + kq;
    ((__half2*)(o + off))[0] = __halves2half2(__float2half_rn(w.x), __float2half_rn(w.y));
    ((__half2*)(o + off))[1] = __halves2half2(__float2half_rn(w.z), __float2half_rn(w.w));
}

// ===================== mma.sync vocab GEMM (fp16, 1-term) =====================
#define VK_PAD    40
#define VK_TILE   (128 * VK_PAD * 2)
#define VK_STAGE  (2 * VK_TILE)
#define VK_NSTAGE 4
#define VK_SMEM   (VK_NSTAGE * VK_STAGE)   // 81920

__global__ __launch_bounds__(256, 2)
void vocab_mma(const __half* __restrict__ gA,
               const __half* __restrict__ gB1, const __half* __restrict__ gB2,
               const float* __restrict__ bias1, const float* __restrict__ bias2,
               float* __restrict__ C1, float* __restrict__ C2)
{
    extern __shared__ __align__(16) char smem_raw[];
    const __half* gB = blockIdx.z ? gB2 : gB1;
    const float* bias = blockIdx.z ? bias2 : bias1;
    float* C = blockIdx.z ? C2 : C1;

    const int tid  = threadIdx.x;
    const int warp = tid >> 5, lane = tid & 31;
    const int wm = warp >> 2, wn = warp & 3;
    const int m0 = blockIdx.y * 128, n0 = blockIdx.x * 128;

    const uint32_t sbase = smem_u32(smem_raw);

    const int lrow = tid >> 1;
    const int lhal = tid & 1;

    float acc[4][4][4];
    #pragma unroll
    for (int i = 0; i < 4; i++)
        #pragma unroll
        for (int j = 0; j < 4; j++) {
            acc[i][j][0] = 0.f; acc[i][j][1] = 0.f;
            acc[i][j][2] = 0.f; acc[i][j][3] = 0.f;
        }

    auto issue_stage = [&](int kc) {
        const uint32_t st = sbase + (kc % VK_NSTAGE) * VK_STAGE;
        const size_t gAo = (size_t)(m0 + lrow) * 256 + kc * 32 + lhal * 16;
        const size_t gBo = (size_t)(n0 + lrow) * 256 + kc * 32 + lhal * 16;
        const uint32_t sd = st + lrow * (VK_PAD * 2) + lhal * 32;
        cp_async16(sd + 0 * VK_TILE,      gA + gAo);
        cp_async16(sd + 0 * VK_TILE + 16, gA + gAo + 8);
        cp_async16(sd + 1 * VK_TILE,      gB + gBo);
        cp_async16(sd + 1 * VK_TILE + 16, gB + gBo + 8);
    };

    issue_stage(0); CP_COMMIT();
    issue_stage(1); CP_COMMIT();
    issue_stage(2); CP_COMMIT();

    const uint32_t ar = wm * 64 + (lane & 15);
    const uint32_t ac16 = (lane >> 4) * 8;
    const int g = lane >> 3, r8 = lane & 7;
    const uint32_t br = wn * 32 + ((g >> 1) * 8) + r8;
    const uint32_t bc = (g & 1) * 8;

    #pragma unroll
    for (int kc = 0; kc < 8; kc++) {
        if (kc < 5)      { issue_stage(kc + 3); CP_COMMIT(); CP_WAIT(3); }
        else if (kc == 5){ CP_WAIT(2); }
        else if (kc == 6){ CP_WAIT(1); }
        else             { CP_WAIT(0); }
        __syncthreads();

        const uint32_t st = sbase + (kc % VK_NSTAGE) * VK_STAGE;
        const uint32_t tA = st;
        const uint32_t tB = st + VK_TILE;

        #pragma unroll
        for (int h = 0; h < 2; h++) {
            uint32_t a[4][4], b[2][4];
            #pragma unroll
            for (int fm = 0; fm < 4; fm++)
                ldsm4(a[fm], tA + ((ar + fm * 16) * VK_PAD + ac16 + h * 16) * 2);
            #pragma unroll
            for (int p = 0; p < 2; p++)
                ldsm4(b[p], tB + ((br + p * 16) * VK_PAD + bc + h * 16) * 2);

            #pragma unroll
            for (int fm = 0; fm < 4; fm++)
                #pragma unroll
                for (int fn = 0; fn < 4; fn++) {
                    const int p = fn >> 1, q = fn & 1;
                    mma16816h(acc[fm][fn], a[fm], b[p][q * 2], b[p][q * 2 + 1]);
                }
        }
        __syncthreads();
    }

    float2 bv[4];
    #pragma unroll
    for (int fn = 0; fn < 4; fn++)
        bv[fn] = *(const float2*)(bias + n0 + wn * 32 + fn * 8 + (lane & 3) * 2);

    #pragma unroll
    for (int fm = 0; fm < 4; fm++) {
        const int r0 = m0 + wm * 64 + fm * 16 + (lane >> 2);
        #pragma unroll
        for (int fn = 0; fn < 4; fn++) {
            const int col = n0 + wn * 32 + fn * 8 + (lane & 3) * 2;
            float2 v0 = make_float2(acc[fm][fn][0] + bv[fn].x, acc[fm][fn][1] + bv[fn].y);
            float2 v1 = make_float2(acc[fm][fn][2] + bv[fn].x, acc[fm][fn][3] + bv[fn].y);
            *(float2*)(C + (size_t)r0 * VOCAB + col)       = v0;
            *(float2*)(C + (size_t)(r0 + 8) * VOCAB + col) = v1;
        }
    }
}

// ===================== row L2-normalize =====================
__global__ __launch_bounds__(256)
void normalize_rows(float* __restrict__ X)
{
    int w = (blockIdx.x * blockDim.x + threadIdx.x) >> 5;
    int lane = threadIdx.x & 31;
    if (w >= M_ROWS) return;
    float* row = X + (size_t)w * D_MEM;
    float x[8];
    float ss = 0.f;
    #pragma unroll
    for (int j = 0; j < 8; j++) { x[j] = row[lane + 32 * j]; ss += x[j] * x[j]; }
    #pragma unroll
    for (int o = 16; o; o >>= 1) ss += __shfl_xor_sync(0xffffffffu, ss, o);
    float inv = 1.f / fmaxf(sqrtf(ss), 1e-12f);
    #pragma unroll
    for (int j = 0; j < 8; j++) row[lane + 32 * j] = x[j] * inv;
}

// ===================== k-neighbor Gram precompute (dist 1..4, packed) =========
// Gv[b][t] = (k_{t-1}.k_t, k_{t-2}.k_t, k_{t-3}.k_t, k_{t-4}.k_t), 0 if t<i.
__global__ __launch_bounds__(256)
void gram_kernel(const float* __restrict__ Kn, float4* __restrict__ Gv)
{
    int w = (blockIdx.x * blockDim.x + threadIdx.x) >> 5;  // 0..2047
    int lane = threadIdx.x & 31;
    int b = w >> 10, t = w & 1023;
    const float* kt = Kn + (size_t)b * T_SEQ * D_MEM + (size_t)t * D_MEM + lane;
    float d1 = 0.f, d2 = 0.f, d3 = 0.f, d4 = 0.f;
    #pragma unroll
    for (int j = 0; j < 8; j++) {
        float a0 = kt[32 * j];
        float p1 = (t >= 1) ? kt[32 * j - 1 * D_MEM] : 0.f;
        float p2 = (t >= 2) ? kt[32 * j - 2 * D_MEM] : 0.f;
        float p3 = (t >= 3) ? kt[32 * j - 3 * D_MEM] : 0.f;
        float p4 = (t >= 4) ? kt[32 * j - 4 * D_MEM] : 0.f;
        d1 = fmaf(a0, p1, d1);
        d2 = fmaf(a0, p2, d2);
        d3 = fmaf(a0, p3, d3);
        d4 = fmaf(a0, p4, d4);
    }
    #pragma unroll
    for (int o = 16; o; o >>= 1) {
        d1 += __shfl_xor_sync(0xffffffffu, d1, o);
        d2 += __shfl_xor_sync(0xffffffffu, d2, o);
        d3 += __shfl_xor_sync(0xffffffffu, d3, o);
        d4 += __shfl_xor_sync(0xffffffffu, d4, o);
    }
    if (lane == 0) Gv[w] = make_float4(d1, d2, d3, d4);
}

// ===================== gated delta-rule scan (dist-4, ring-8 prefetch) ========
// read_s = t1234*D_s + (t123*c4)*G4_s + (t12*c3)*G3_s + (t1*c2)*G2_s + c1*G1_s
// D_s = M^(s-4).k_s. Ring-of-8: slot S%8 consumed at body S, refilled with
// step S+8 immediately after its last use; the D-partial read of k_{S+4}
// hits a slot refilled 4 bodies earlier (~500 cyc of load-latency cover).
#define SCAN_BODY(C, C4, S) do {                                              \
    float ua_ = 0.f, ub_ = 0.f;                                               \
    _Pragma("unroll")                                                         \
    for (int j = 0; j < 8; j += 2) {                                          \
        ua_ = fmaf(m[j], kr##C4[j], ua_);                                     \
        ub_ = fmaf(m[j + 1], kr##C4[j + 1], ub_);                             \
    }                                                                         \
    float base_ = fmaf(t1234, Dcur, (t123 * c4) * gr##C.w);                   \
    base_ = fmaf(t12 * c3, gr##C.z, base_);                                   \
    base_ = fmaf(t1 * c2, gr##C.y, base_);                                    \
    const float read_ = fmaf(c1, gr##C.x, base_);                             \
    const float lt_ = lr##C;                                                  \
    const float corr_ = (vr##C - read_) * br##C;                              \
    if (lane == 0) sb[(size_t)(S) * D_MEM] = fmaf(lt_, read_, corr_);         \
    _Pragma("unroll")                                                         \
    for (int j = 0; j < 8; j++)                                               \
        m[j] = fmaf(m[j], lt_, corr_ * kr##C[j]);                             \
    {                                                                         \
        const int ii_ = ((S) + 8 < T_SEQ) ? (S) + 8 : (T_SEQ - 1);            \
        _Pragma("unroll")                                                     \
        for (int j = 0; j < 8; j++)                                           \
            kr##C[j] = kb[(size_t)ii_ * D_MEM + 32 * j];                      \
        vr##C = vb[(size_t)ii_ * D_MEM];                                      \
        br##C = bbp[(size_t)ii_ * D_MEM];                                     \
        lr##C = lb[(size_t)ii_ * D_MEM];                                      \
        gr##C = gb[ii_];                                                      \
    }                                                                         \
    _Pragma("unroll")                                                         \
    for (int o = 16; o; o >>= 1) {                                            \
        ua_ += __shfl_xor_sync(0xffffffffu, ua_, o);                          \
        ub_ += __shfl_xor_sync(0xffffffffu, ub_, o);                          \
    }                                                                         \
    Dcur = Dn1; Dn1 = Dn2; Dn2 = Dn3; Dn3 = ua_ + ub_;                        \
    c4 = c3; c3 = c2; c2 = c1; c1 = corr_;                                    \
    t1234 = lt_ * t123; t123 = lt_ * t12; t12 = lt_ * t1; t1 = lt_;           \
} while (0)

#define RELOAD_SLOT(C, II) do {                                               \
    _Pragma("unroll")                                                         \
    for (int j = 0; j < 8; j++) kr##C[j] = kb[(size_t)(II) * D_MEM + 32 * j]; \
    vr##C = vb[(size_t)(II) * D_MEM];                                         \
    br##C = bbp[(size_t)(II) * D_MEM];                                        \
    lr##C = lb[(size_t)(II) * D_MEM];                                         \
    gr##C = gb[II];                                                           \
} while (0)

__global__ __launch_bounds__(128)
void scan_kernel(const float* __restrict__ Kn, const float* __restrict__ V,
                 const float* __restrict__ Beta, const float* __restrict__ Lam,
                 const float4* __restrict__ Gv,
                 const float* __restrict__ Mem0, float* __restrict__ Sraw,
                 float* __restrict__ MemOut)
{
    const int wid  = threadIdx.x >> 5;
    const int lane = threadIdx.x & 31;
    const int wg = blockIdx.x * 4 + wid;
    const int b = wg >> 8;
    const int r = wg & 255;

    const float* kb  = Kn   + (size_t)b * T_SEQ * D_MEM + lane;
    const float* vb  = V    + (size_t)b * T_SEQ * D_MEM + r;
    const float* bbp = Beta + (size_t)b * T_SEQ * D_MEM + r;
    const float* lb  = Lam  + (size_t)b * T_SEQ * D_MEM + r;
    const float4* gb = Gv + (size_t)b * T_SEQ;
    float* sb = Sraw + (size_t)b * T_SEQ * D_MEM + r;

    float m[8];
    #pragma unroll
    for (int j = 0; j < 8; j++)
        m[j] = Mem0[(size_t)b * D_MEM * D_MEM + (size_t)r * D_MEM + lane + 32 * j];

    // rings of 8 (all static)
    float kr0[8], kr1[8], kr2[8], kr3[8], kr4[8], kr5[8], kr6[8], kr7[8];
    float vr0, vr1, vr2, vr3, vr4, vr5, vr6, vr7;
    float br0, br1, br2, br3, br4, br5, br6, br7;
    float lr0, lr1, lr2, lr3, lr4, lr5, lr6, lr7;
    float4 gr0, gr1, gr2, gr3, gr4, gr5, gr6, gr7;
    RELOAD_SLOT(0, 0); RELOAD_SLOT(1, 1); RELOAD_SLOT(2, 2); RELOAD_SLOT(3, 3);
    RELOAD_SLOT(4, 4); RELOAD_SLOT(5, 5); RELOAD_SLOT(6, 6); RELOAD_SLOT(7, 7);

    // ---- boot block: A_i = M^(0).k_i for i = 0..4 (5 interleaved reductions)
    float A0 = 0.f, A1 = 0.f, A2 = 0.f, A3 = 0.f, A4 = 0.f;
    #pragma unroll
    for (int j = 0; j < 8; j++) {
        A0 = fmaf(m[j], kr0[j], A0);
        A1 = fmaf(m[j], kr1[j], A1);
        A2 = fmaf(m[j], kr2[j], A2);
        A3 = fmaf(m[j], kr3[j], A3);
        A4 = fmaf(m[j], kr4[j], A4);
    }
    #pragma unroll
    for (int o = 16; o; o >>= 1) {
        A0 += __shfl_xor_sync(0xffffffffu, A0, o);
        A1 += __shfl_xor_sync(0xffffffffu, A1, o);
        A2 += __shfl_xor_sync(0xffffffffu, A2, o);
        A3 += __shfl_xor_sync(0xffffffffu, A3, o);
        A4 += __shfl_xor_sync(0xffffffffu, A4, o);
    }

    // ---- boot step 0 ----
    const float l0s = lr0;
    const float read0 = A0;
    const float corr0 = (vr0 - read0) * br0;
    if (lane == 0) sb[0] = fmaf(l0s, read0, corr0);
    #pragma unroll
    for (int j = 0; j < 8; j++) m[j] = fmaf(m[j], l0s, corr0 * kr0[j]);   // M^(1)
    RELOAD_SLOT(0, 8);

    // ---- boot step 1 (D5 partials on M^(1) with k5 in slot 5) ----
    float u5a = 0.f, u5b = 0.f;
    #pragma unroll
    for (int j = 0; j < 8; j += 2) {
        u5a = fmaf(m[j], kr5[j], u5a);
        u5b = fmaf(m[j + 1], kr5[j + 1], u5b);
    }
    const float l1s = lr1;
    const float read1 = fmaf(l0s, A1, corr0 * gr1.x);
    const float corr1 = (vr1 - read1) * br1;
    if (lane == 0) sb[D_MEM] = fmaf(l1s, read1, corr1);
    #pragma unroll
    for (int j = 0; j < 8; j++) m[j] = fmaf(m[j], l1s, corr1 * kr1[j]);   // M^(2)
    #pragma unroll
    for (int o = 16; o; o >>= 1) {
        u5a += __shfl_xor_sync(0xffffffffu, u5a, o);
        u5b += __shfl_xor_sync(0xffffffffu, u5b, o);
    }
    const float D5 = u5a + u5b;
    RELOAD_SLOT(1, 9);

    // ---- boot step 2 (D6 partials on M^(2) with k6 in slot 6) ----
    float u6a = 0.f, u6b = 0.f;
    #pragma unroll
    for (int j = 0; j < 8; j += 2) {
        u6a = fmaf(m[j], kr6[j], u6a);
        u6b = fmaf(m[j + 1], kr6[j + 1], u6b);
    }
    const float l2s = lr2;
    const float read2 = fmaf(l1s, fmaf(l0s, A2, corr0 * gr2.y), corr1 * gr2.x);
    const float corr2 = (vr2 - read2) * br2;
    if (lane == 0) sb[2 * D_MEM] = fmaf(l2s, read2, corr2);
    #pragma unroll
    for (int j = 0; j < 8; j++) m[j] = fmaf(m[j], l2s, corr2 * kr2[j]);   // M^(3)
    #pragma unroll
    for (int o = 16; o; o >>= 1) {
        u6a += __shfl_xor_sync(0xffffffffu, u6a, o);
        u6b += __shfl_xor_sync(0xffffffffu, u6b, o);
    }
    const float D6 = u6a + u6b;
    RELOAD_SLOT(2, 10);

    // ---- boot step 3 (D7 partials on M^(3) with k7 in slot 7) ----
    float u7a = 0.f, u7b = 0.f;
    #pragma unroll
    for (int j = 0; j < 8; j += 2) {
        u7a = fmaf(m[j], kr7[j], u7a);
        u7b = fmaf(m[j + 1], kr7[j + 1], u7b);
    }
    const float l3s = lr3;
    float in3 = fmaf(l1s, fmaf(l0s, A3, corr0 * gr3.z), corr1 * gr3.y);
    const float read3 = fmaf(l2s, in3, corr2 * gr3.x);
    const float corr3 = (vr3 - read3) * br3;
    if (lane == 0) sb[3 * D_MEM] = fmaf(l3s, read3, corr3);
    #pragma unroll
    for (int j = 0; j < 8; j++) m[j] = fmaf(m[j], l3s, corr3 * kr3[j]);   // M^(4)
    #pragma unroll
    for (int o = 16; o; o >>= 1) {
        u7a += __shfl_xor_sync(0xffffffffu, u7a, o);
        u7b += __shfl_xor_sync(0xffffffffu, u7b, o);
    }
    const float D7 = u7a + u7b;
    RELOAD_SLOT(3, 11);

    // ---- seed steady-state scalars (entering s = 4) ----
    float Dcur = A4, Dn1 = D5, Dn2 = D6, Dn3 = D7;
    float c1 = corr3, c2 = corr2, c3 = corr1, c4 = corr0;
    float t1 = l3s;
    float t12 = l3s * l2s;
    float t123 = t12 * l1s;
    float t1234 = t123 * l0s;

    // ---- steady loop: s = 4 .. 1019 (1016 = 127 * 8), tail 1020..1023 ----
    for (int s = 4; s <= 1012; s += 8) {
        SCAN_BODY(4, 0, s);
        SCAN_BODY(5, 1, s + 1);
        SCAN_BODY(6, 2, s + 2);
        SCAN_BODY(7, 3, s + 3);
        SCAN_BODY(0, 4, s + 4);
        SCAN_BODY(1, 5, s + 5);
        SCAN_BODY(2, 6, s + 6);
        SCAN_BODY(3, 7, s + 7);
    }
    SCAN_BODY(4, 0, 1020);
    SCAN_BODY(5, 1, 1021);
    SCAN_BODY(6, 2, 1022);
    SCAN_BODY(7, 3, 1023);

    #pragma unroll
    for (int j = 0; j < 8; j++)
        MemOut[(size_t)b * D_MEM * D_MEM + (size_t)r * D_MEM + lane + 32 * j] = m[j];
}

// ===================== launch =====================
extern "C" void kernel_launch(void* const* d_in, const int* in_sizes, int n_in,
                              void* d_out, int out_size)
{
    const float* cf    = (const float*)d_in[0];
    const float* mem0  = (const float*)d_in[1];
    const float* Wk    = (const float*)d_in[2];
    const float* bk    = (const float*)d_in[3];
    const float* Wv    = (const float*)d_in[4];
    const float* bv    = (const float*)d_in[5];
    const float* Wbeta = (const float*)d_in[6];
    const float* bbeta = (const float*)d_in[7];
    const float* Wlam  = (const float*)d_in[8];
    const float* blam  = (const float*)d_in[9];
    const float* Wsum  = (const float*)d_in[10];
    const float* bsum  = (const float*)d_in[11];
    const float* Wlb   = (const float*)d_in[12];
    const float* blb   = (const float*)d_in[13];
    const float* Wph   = (const float*)d_in[14];
    const float* bph   = (const float*)d_in[15];
    const float* Wwin  = (const float*)d_in[16];
    const float* bwin  = (const float*)d_in[17];
    const float* Wmar  = (const float*)d_in[18];
    const float* bmar  = (const float*)d_in[19];

    float* out = (float*)d_out;
    float* out_mem = out + OFF_MEM;
    float* out_sum = out + OFF_SUM;
    float* out_lb  = out + OFF_LB;
    float* out_ph  = out + OFF_PH;
    float* out_win = out + OFF_WIN;
    float* out_mar = out + OFF_MAR;

    float *pk, *pv, *pb, *pl, *ps;
    float4* pGv;
    __half *pA16, *pW1, *pW2;
    cudaGetSymbolAddress((void**)&pk, g_k);
    cudaGetSymbolAddress((void**)&pv, g_v);
    cudaGetSymbolAddress((void**)&pb, g_beta);
    cudaGetSymbolAddress((void**)&pl, g_lam);
    cudaGetSymbolAddress((void**)&ps, g_sraw);
    cudaGetSymbolAddress((void**)&pGv, g_Gv);
    cudaGetSymbolAddress((void**)&pA16, g_A16);
    cudaGetSymbolAddress((void**)&pW1, g_W1f);
    cudaGetSymbolAddress((void**)&pW2, g_W2f);

    cudaFuncSetAttribute(vocab_mma, cudaFuncAttributeMaxDynamicSharedMemorySize, VK_SMEM);

    // weight pre-convert (merged; independent of the recurrence path)
    convert_w16<<<dim3(8000, 1, 2), 256>>>(Wlb, Wwin, pW1, pW2);

    // projections (merged)
    proj_gemm<<<dim3(4, 32, 4), 256>>>(cf, Wk, Wv, Wbeta, Wlam,
                                       bk, bv, bbeta, blam,
                                       pk, pv, pb, pl);

    normalize_rows<<<256, 256>>>(pk);

    // k-neighbor Gram terms (dist 1..4, packed float4)
    gram_kernel<<<256, 256>>>(pk, pGv);

    scan_kernel<<<128, 128>>>(pk, pv, pb, pl, pGv, mem0, ps, out_mem);

    // summary GEMM (tanh) + fp16 side output
    gemm_bias_act<2, true><<<dim3(4, 32), 256>>>(ps, Wsum, bsum, out_sum,
                                                 M_ROWS, D_MEM, D_MEM, pA16);

    // both vocab GEMMs in one launch (grid.z selects head)
    vocab_mma<<<dim3(250, 16, 2), 256, VK_SMEM>>>(pA16, pW1, pW2, blb, bwin,
                                                  out_lb, out_win);

    // small heads
    gemm_bias_act<0, false><<<dim3(1, 32), 256>>>(out_sum, Wph,  bph,  out_ph,
                                                  M_ROWS, PHASE_N, D_MEM, nullptr);
    gemm_bias_act<0, false><<<dim3(1, 32), 256>>>(out_sum, Wmar, bmar, out_mar,
                                                  M_ROWS, MARGIN_N, D_MEM, nullptr);
}